// round 2
// baseline (speedup 1.0000x reference)
#include <cuda_runtime.h>
#include <cuda_bf16.h>
#include <cstdint>

// Problem constants
#define NNODES 100000
#define NEDGES 1600000
#define DIN 128
#define DH 128
#define DOUT 64

// ---------------- scratch (device globals; no allocation allowed) -------------
__device__ int   g_deg[NNODES];          // in-degree + 1 (self loop)
__device__ float g_dinv[NNODES];         // rsqrt(deg)
__device__ int   g_off[NNODES];          // CSR offsets (exclusive scan of in-degree)
__device__ int   g_cursor[NNODES];       // scatter cursors
__device__ int   g_csr_src[NEDGES];      // CSR column (src node)
__device__ float g_csr_w[NEDGES];        // precomputed dinv[s]*dinv[d]
__device__ float g_bufA[(size_t)NNODES * DIN];
__device__ float g_bufB[(size_t)NNODES * DIN];

#define SCAN_CHUNK 1024
#define SCAN_BLOCKS 98               // ceil(100000/1024)
__device__ int g_bsum[SCAN_BLOCKS];

// ---------------- f32x2 helpers ----------------------------------------------
__device__ __forceinline__ unsigned long long pack2(float lo, float hi) {
    unsigned long long r;
    asm("mov.b64 %0, {%1, %2};" : "=l"(r) : "f"(lo), "f"(hi));
    return r;
}
__device__ __forceinline__ void unpack2(unsigned long long v, float& lo, float& hi) {
    asm("mov.b64 {%0, %1}, %2;" : "=f"(lo), "=f"(hi) : "l"(v));
}
#define FMA_F32X2(d, a, b, c) \
    asm("fma.rn.f32x2 %0, %1, %2, %3;" : "=l"(d) : "l"(a), "l"(b), "l"(c))

// ---------------- CSR build ---------------------------------------------------
__global__ void k_init(void) {
    int v = blockIdx.x * blockDim.x + threadIdx.x;
    if (v < NNODES) { g_deg[v] = 1; g_cursor[v] = 0; }
}

__global__ void k_count(const int* __restrict__ dst) {
    int e = blockIdx.x * blockDim.x + threadIdx.x;
    if (e < NEDGES) atomicAdd(&g_deg[dst[e]], 1);
}

__global__ void k_dinv(void) {
    int v = blockIdx.x * blockDim.x + threadIdx.x;
    if (v < NNODES) g_dinv[v] = rsqrtf((float)g_deg[v]);
}

// exclusive scan of (deg-1) : 3 phases
__global__ void k_scan_block(void) {
    __shared__ int wsum[8];
    int tid = threadIdx.x;
    int base = blockIdx.x * SCAN_CHUNK + tid * 4;
    int v[4];
#pragma unroll
    for (int i = 0; i < 4; i++) {
        int idx = base + i;
        v[i] = (idx < NNODES) ? (g_deg[idx] - 1) : 0;
    }
    int e0 = 0, e1 = v[0], e2 = v[0] + v[1], e3 = v[0] + v[1] + v[2];
    int tot = e3 + v[3];
    int lane = tid & 31, wid = tid >> 5;
    int x = tot;
#pragma unroll
    for (int off = 1; off < 32; off <<= 1) {
        int y = __shfl_up_sync(0xFFFFFFFFu, x, off);
        if (lane >= off) x += y;
    }
    if (lane == 31) wsum[wid] = x;
    __syncthreads();
    if (wid == 0) {
        int t = (lane < 8) ? wsum[lane] : 0;
        int xx = t;
#pragma unroll
        for (int off = 1; off < 8; off <<= 1) {
            int y = __shfl_up_sync(0xFFFFFFFFu, xx, off);
            if (lane >= off) xx += y;
        }
        if (lane < 8) wsum[lane] = xx - t;   // exclusive
    }
    __syncthreads();
    int texc = wsum[wid] + (x - tot);
    int o0 = texc + e0, o1 = texc + e1, o2 = texc + e2, o3 = texc + e3;
    if (base + 0 < NNODES) g_off[base + 0] = o0;
    if (base + 1 < NNODES) g_off[base + 1] = o1;
    if (base + 2 < NNODES) g_off[base + 2] = o2;
    if (base + 3 < NNODES) g_off[base + 3] = o3;
    if (tid == blockDim.x - 1) g_bsum[blockIdx.x] = texc + tot;
}

__global__ void k_scan_top(void) {
    int acc = 0;
    for (int b = 0; b < SCAN_BLOCKS; b++) {
        int t = g_bsum[b];
        g_bsum[b] = acc;
        acc += t;
    }
}

__global__ void k_scan_add(void) {
    int tid = threadIdx.x;
    int base = blockIdx.x * SCAN_CHUNK + tid * 4;
    int add = g_bsum[blockIdx.x];
#pragma unroll
    for (int i = 0; i < 4; i++) {
        int idx = base + i;
        if (idx < NNODES) g_off[idx] += add;
    }
}

__global__ void k_scatter(const int* __restrict__ src, const int* __restrict__ dst) {
    int e = blockIdx.x * blockDim.x + threadIdx.x;
    if (e >= NEDGES) return;
    int s = src[e], d = dst[e];
    int pos = g_off[d] + atomicAdd(&g_cursor[d], 1);
    g_csr_src[pos] = s;
    g_csr_w[pos] = g_dinv[s] * g_dinv[d];
}

// ---------------- SGEMM with packed f32x2 FMA --------------------------------
// C[M,BN] = A[M,128] @ B[128,BN]
// Thread (ty,tx): rows ty*8 .. ty*8+7 (paired into f32x2 lanes),
// columns { j*16 + tx : j = 0..TN-1 } (strided -> conflict-free LDS + coalesced STG)
template <int BN>
__global__ __launch_bounds__(256) void k_sgemm(const float* __restrict__ A,
                                               const float* __restrict__ B,
                                               float* __restrict__ C, int M) {
    constexpr int BM = 128, BK = 8, TM = 8, TN = BN / 16;
    __shared__ float As[BK][BM + 4];                 // 16B-aligned rows (528B pitch)
    __shared__ unsigned long long Bd[BK][BN];        // duplicated pairs (v,v)

    int tid = threadIdx.x;
    int ty = tid / 16, tx = tid % 16;
    int blockRow = blockIdx.x * BM;

    unsigned long long acc2[TM / 2][TN];
#pragma unroll
    for (int i = 0; i < TM / 2; i++)
#pragma unroll
        for (int j = 0; j < TN; j++) acc2[i][j] = 0ULL;

    int arow = tid >> 1;
    int acol = (tid & 1) * 4;
    int brow = tid / (BN / 4);
    int bcol = (tid % (BN / 4)) * 4;

    for (int k0 = 0; k0 < 128; k0 += BK) {
        float4 a = make_float4(0.f, 0.f, 0.f, 0.f);
        if (blockRow + arow < M)
            a = *reinterpret_cast<const float4*>(&A[(size_t)(blockRow + arow) * 128 + k0 + acol]);
        As[acol + 0][arow] = a.x;
        As[acol + 1][arow] = a.y;
        As[acol + 2][arow] = a.z;
        As[acol + 3][arow] = a.w;

        if (BN == 128 || tid < 128) {
            float4 b = *reinterpret_cast<const float4*>(&B[(size_t)(k0 + brow) * BN + bcol]);
            Bd[brow][bcol + 0] = pack2(b.x, b.x);
            Bd[brow][bcol + 1] = pack2(b.y, b.y);
            Bd[brow][bcol + 2] = pack2(b.z, b.z);
            Bd[brow][bcol + 3] = pack2(b.w, b.w);
        }
        __syncthreads();

#pragma unroll
        for (int kk = 0; kk < BK; kk++) {
            const unsigned long long* ap =
                reinterpret_cast<const unsigned long long*>(&As[kk][ty * TM]);
            unsigned long long a2[TM / 2];
#pragma unroll
            for (int i = 0; i < TM / 2; i++) a2[i] = ap[i];
            unsigned long long b2[TN];
#pragma unroll
            for (int j = 0; j < TN; j++) b2[j] = Bd[kk][j * 16 + tx];
#pragma unroll
            for (int i = 0; i < TM / 2; i++)
#pragma unroll
                for (int j = 0; j < TN; j++)
                    FMA_F32X2(acc2[i][j], a2[i], b2[j], acc2[i][j]);
        }
        __syncthreads();
    }

#pragma unroll
    for (int i = 0; i < TM / 2; i++) {
        int row0 = blockRow + ty * TM + 2 * i;
#pragma unroll
        for (int j = 0; j < TN; j++) {
            float v0, v1;
            unpack2(acc2[i][j], v0, v1);
            int col = j * 16 + tx;
            if (row0 < M)     C[(size_t)row0 * BN + col] = v0;
            if (row0 + 1 < M) C[(size_t)(row0 + 1) * BN + col] = v1;
        }
    }
}

// ---------------- Aggregation: out[v] = sum_{(s,v)} w * h[s] (+self) + bias ---
// one warp per dst node, lane covers DIM/32 contiguous features
template <int DIM, bool RELU>
__global__ __launch_bounds__(256) void k_agg(const float* __restrict__ h,
                                             const float* __restrict__ bias,
                                             float* __restrict__ out) {
    int warp = (blockIdx.x * blockDim.x + threadIdx.x) >> 5;
    if (warp >= NNODES) return;
    int lane = threadIdx.x & 31;

    float dv = g_dinv[warp];
    float wself = dv * dv;
    int beg = g_off[warp];
    int end = beg + (g_deg[warp] - 1);

    if (DIM == 128) {
        const float4* hp = reinterpret_cast<const float4*>(h);
        float4 sv = hp[(size_t)warp * 32 + lane];
        float ax = sv.x * wself, ay = sv.y * wself, az = sv.z * wself, aw = sv.w * wself;
        int e = beg;
        for (; e + 3 < end; e += 4) {
            int s0 = g_csr_src[e],     s1 = g_csr_src[e + 1];
            int s2 = g_csr_src[e + 2], s3 = g_csr_src[e + 3];
            float w0 = g_csr_w[e],     w1 = g_csr_w[e + 1];
            float w2 = g_csr_w[e + 2], w3 = g_csr_w[e + 3];
            float4 v0 = hp[(size_t)s0 * 32 + lane];
            float4 v1 = hp[(size_t)s1 * 32 + lane];
            float4 v2 = hp[(size_t)s2 * 32 + lane];
            float4 v3 = hp[(size_t)s3 * 32 + lane];
            ax += v0.x * w0 + v1.x * w1 + v2.x * w2 + v3.x * w3;
            ay += v0.y * w0 + v1.y * w1 + v2.y * w2 + v3.y * w3;
            az += v0.z * w0 + v1.z * w1 + v2.z * w2 + v3.z * w3;
            aw += v0.w * w0 + v1.w * w1 + v2.w * w2 + v3.w * w3;
        }
        for (; e < end; e++) {
            int s0 = g_csr_src[e];
            float w0 = g_csr_w[e];
            float4 v0 = hp[(size_t)s0 * 32 + lane];
            ax += v0.x * w0; ay += v0.y * w0; az += v0.z * w0; aw += v0.w * w0;
        }
        float4 b4 = reinterpret_cast<const float4*>(bias)[lane];
        ax += b4.x; ay += b4.y; az += b4.z; aw += b4.w;
        if (RELU) {
            ax = fmaxf(ax, 0.f); ay = fmaxf(ay, 0.f);
            az = fmaxf(az, 0.f); aw = fmaxf(aw, 0.f);
        }
        float4 o; o.x = ax; o.y = ay; o.z = az; o.w = aw;
        reinterpret_cast<float4*>(out)[(size_t)warp * 32 + lane] = o;
    } else {  // DIM == 64
        const float2* hp = reinterpret_cast<const float2*>(h);
        float2 sv = hp[(size_t)warp * 32 + lane];
        float ax = sv.x * wself, ay = sv.y * wself;
        int e = beg;
        for (; e + 3 < end; e += 4) {
            int s0 = g_csr_src[e],     s1 = g_csr_src[e + 1];
            int s2 = g_csr_src[e + 2], s3 = g_csr_src[e + 3];
            float w0 = g_csr_w[e],     w1 = g_csr_w[e + 1];
            float w2 = g_csr_w[e + 2], w3 = g_csr_w[e + 3];
            float2 v0 = hp[(size_t)s0 * 32 + lane];
            float2 v1 = hp[(size_t)s1 * 32 + lane];
            float2 v2 = hp[(size_t)s2 * 32 + lane];
            float2 v3 = hp[(size_t)s3 * 32 + lane];
            ax += v0.x * w0 + v1.x * w1 + v2.x * w2 + v3.x * w3;
            ay += v0.y * w0 + v1.y * w1 + v2.y * w2 + v3.y * w3;
        }
        for (; e < end; e++) {
            int s0 = g_csr_src[e];
            float w0 = g_csr_w[e];
            float2 v0 = hp[(size_t)s0 * 32 + lane];
            ax += v0.x * w0; ay += v0.y * w0;
        }
        float2 b2 = reinterpret_cast<const float2*>(bias)[lane];
        ax += b2.x; ay += b2.y;
        if (RELU) { ax = fmaxf(ax, 0.f); ay = fmaxf(ay, 0.f); }
        float2 o; o.x = ax; o.y = ay;
        reinterpret_cast<float2*>(out)[(size_t)warp * 32 + lane] = o;
    }
}

// ---------------- launch ------------------------------------------------------
extern "C" void kernel_launch(void* const* d_in, const int* in_sizes, int n_in,
                              void* d_out, int out_size) {
    const float* x  = (const float*)d_in[0];
    const int*   ei = (const int*)d_in[1];
    const float* W1 = (const float*)d_in[2];
    const float* b1 = (const float*)d_in[3];
    const float* W2 = (const float*)d_in[4];
    const float* b2 = (const float*)d_in[5];
    const float* W3 = (const float*)d_in[6];
    const float* b3 = (const float*)d_in[7];
    float* out = (float*)d_out;

    const int* src = ei;
    const int* dst = ei + NEDGES;

    float* bufA; cudaGetSymbolAddress((void**)&bufA, g_bufA);
    float* bufB; cudaGetSymbolAddress((void**)&bufB, g_bufB);

    const int TB = 256;
    int nodeBlocks = (NNODES + TB - 1) / TB;   // 391
    int edgeBlocks = (NEDGES + TB - 1) / TB;   // 6250
    int gemmBlocks = (NNODES + 127) / 128;     // 782
    int aggBlocks  = (NNODES + 7) / 8;         // 12500 (8 warps/block)

    // graph preprocessing (shared across layers)
    k_init<<<nodeBlocks, TB>>>();
    k_count<<<edgeBlocks, TB>>>(dst);
    k_dinv<<<nodeBlocks, TB>>>();
    k_scan_block<<<SCAN_BLOCKS, TB>>>();
    k_scan_top<<<1, 1>>>();
    k_scan_add<<<SCAN_BLOCKS, TB>>>();
    k_scatter<<<edgeBlocks, TB>>>(src, dst);

    // layer 1: agg(x@W1)+b1 -> relu
    k_sgemm<128><<<gemmBlocks, TB>>>(x, W1, bufA, NNODES);
    k_agg<128, true><<<aggBlocks, TB>>>(bufA, b1, bufB);
    // layer 2
    k_sgemm<128><<<gemmBlocks, TB>>>(bufB, W2, bufA, NNODES);
    k_agg<128, true><<<aggBlocks, TB>>>(bufA, b2, bufB);
    // layer 3 (transform first: 64-dim aggregation)
    k_sgemm<64><<<gemmBlocks, TB>>>(bufB, W3, bufA, NNODES);
    k_agg<64, false><<<aggBlocks, TB>>>(bufA, b3, out);
}